// round 3
// baseline (speedup 1.0000x reference)
#include <cuda_runtime.h>

#define NMAX 100000
#define EMAX 1600000

// Scratch (allocation-free rule: __device__ globals)
__device__ int   g_is64;           // 1 if edge_index buffer is int64, else int32
__device__ int   g_deg[NMAX];      // in-degree incl self-loop
__device__ float g_dinv[NMAX];
__device__ int   g_off[NMAX];      // CSR row start (real edges only)
__device__ int   g_cur[NMAX];      // fill cursors
__device__ int   g_csr[EMAX];      // src node per CSR slot
__device__ float g_t[NMAX * 64];   // t1 = x@W1, later t2 = relu(h)@W2
__device__ float g_h[NMAX * 64];   // layer-1 aggregated output

// ---------------------------------------------------------------------------
// Detect int32 vs int64 edge_index. Node ids < 100000 fit in 32 bits, so a
// genuine int64 buffer has every odd 32-bit word == 0. For random int32 data
// the probability of that is ~0.
__global__ void k_detect(const unsigned int* __restrict__ w) {
    if (threadIdx.x == 0) {
        int nz = 0;
        for (int i = 1; i < 2048; i += 2) nz += (w[i] != 0u);
        g_is64 = (nz == 0) ? 1 : 0;
    }
}

__device__ __forceinline__ int load_idx(const void* ei, long long i) {
    if (g_is64) return (int)((const long long*)ei)[i];
    return ((const int*)ei)[i];
}

__global__ void k_deg_init(int n) {
    int i = blockIdx.x * blockDim.x + threadIdx.x;
    if (i < n) g_deg[i] = 1;  // self-loop
}

__global__ void k_count(const void* __restrict__ ei, int e, int n) {
    int i = blockIdx.x * blockDim.x + threadIdx.x;
    if (i >= e) return;
    int d = load_idx(ei, (long long)e + i);
    if ((unsigned)d < (unsigned)n) atomicAdd(&g_deg[d], 1);
}

// Single-block exclusive scan of (deg-1) over n nodes -> g_off, g_cur; also dinv.
__global__ void k_scan(int n) {
    __shared__ int part[1024];
    __shared__ int pexcl[1024];
    int t = threadIdx.x;
    int chunk = (n + 1023) >> 10;
    int lo = t * chunk;
    int hi = lo + chunk; if (hi > n) hi = n;
    int s = 0;
    for (int i = lo; i < hi; i++) s += g_deg[i] - 1;
    part[t] = s;
    __syncthreads();
    if (t == 0) {
        int run = 0;
        for (int i = 0; i < 1024; i++) { pexcl[i] = run; run += part[i]; }
    }
    __syncthreads();
    int run = pexcl[t];
    for (int i = lo; i < hi; i++) {
        g_off[i] = run;
        g_cur[i] = run;
        int d = g_deg[i];
        run += d - 1;
        g_dinv[i] = rsqrtf((float)d);
    }
}

__global__ void k_fill(const void* __restrict__ ei, int e, int n) {
    int i = blockIdx.x * blockDim.x + threadIdx.x;
    if (i >= e) return;
    int s = load_idx(ei, i);
    int d = load_idx(ei, (long long)e + i);
    if ((unsigned)s >= (unsigned)n || (unsigned)d >= (unsigned)n) return;
    int pos = atomicAdd(&g_cur[d], 1);
    if ((unsigned)pos < (unsigned)EMAX) g_csr[pos] = s;
}

// ---------------------------------------------------------------------------
// GEMM1: g_t = x @ W1   (x: [n,128], W1: [128,64])
// block = 256 threads, 32 rows x 64 cols per block, 8 rows per thread.
__global__ void k_gemm1(const float* __restrict__ x, const float* __restrict__ W,
                        int n) {
    __shared__ float xs[32 * 129];
    __shared__ float ws[64 * 64];
    int tx = threadIdx.x;
    int row0 = blockIdx.x * 32;

    for (int i = tx; i < 32 * 128; i += 256) {
        int r = i >> 7, k = i & 127;
        int gr = row0 + r;
        xs[r * 129 + k] = (gr < n) ? x[gr * 128 + k] : 0.f;
    }

    int c = tx & 63, y = tx >> 6;
    float acc[8];
#pragma unroll
    for (int i = 0; i < 8; i++) acc[i] = 0.f;

    for (int kb = 0; kb < 128; kb += 64) {
        __syncthreads();
        for (int i = tx; i < 64 * 64; i += 256) ws[i] = W[kb * 64 + i];
        __syncthreads();
        for (int k = 0; k < 64; ++k) {
            float w = ws[k * 64 + c];
#pragma unroll
            for (int i = 0; i < 8; i++)
                acc[i] += xs[(y * 8 + i) * 129 + kb + k] * w;
        }
    }
#pragma unroll
    for (int i = 0; i < 8; i++) {
        int gr = row0 + y * 8 + i;
        if (gr < n) g_t[gr * 64 + c] = acc[i];
    }
}

// GEMM2: g_t = relu(g_h + b1) @ W2   (fused relu+bias on load)
__global__ void k_gemm2(const float* __restrict__ W2, const float* __restrict__ b1,
                        int n) {
    __shared__ float hs[32 * 65];
    __shared__ float ws[64 * 64];
    int tx = threadIdx.x;
    int row0 = blockIdx.x * 32;

    for (int i = tx; i < 64 * 64; i += 256) ws[i] = W2[i];
    for (int i = tx; i < 32 * 64; i += 256) {
        int r = i >> 6, k = i & 63;
        int gr = row0 + r;
        float v = (gr < n) ? (g_h[gr * 64 + k] + b1[k]) : 0.f;
        hs[r * 65 + k] = fmaxf(v, 0.f);
    }
    __syncthreads();

    int c = tx & 63, y = tx >> 6;
    float acc[8];
#pragma unroll
    for (int i = 0; i < 8; i++) acc[i] = 0.f;

    for (int k = 0; k < 64; ++k) {
        float w = ws[k * 64 + c];
#pragma unroll
        for (int i = 0; i < 8; i++)
            acc[i] += hs[(y * 8 + i) * 65 + k] * w;
    }
#pragma unroll
    for (int i = 0; i < 8; i++) {
        int gr = row0 + y * 8 + i;
        if (gr < n) g_t[gr * 64 + c] = acc[i];
    }
}

// ---------------------------------------------------------------------------
// Pull-mode aggregation: 64 threads per dst node, thread c owns feature c.
//   out[d][c] = dinv[d] * ( t[d][c]*dinv[d] + sum_{s in N(d)} t[s][c]*dinv[s] )
// FINAL adds bias b and writes to `out` (un-poisons d_out); else writes g_h.
template <bool FINAL>
__global__ void k_agg(int n, const float* __restrict__ bias,
                      float* __restrict__ out) {
    int gid = blockIdx.x * 4 + (threadIdx.x >> 6);
    int c = threadIdx.x & 63;
    if (gid >= n) return;

    float dd  = g_dinv[gid];
    float acc = g_t[gid * 64 + c] * dd;   // self-loop term (one dinv factor)
    int beg = g_off[gid];
    int end = beg + g_deg[gid] - 1;
#pragma unroll 4
    for (int k = beg; k < end; k++) {
        int s = g_csr[k];
        acc += g_t[s * 64 + c] * g_dinv[s];
    }
    acc *= dd;
    if (FINAL) out[gid * 64 + c] = acc + bias[c];
    else       g_h[gid * 64 + c] = acc;
}

// ---------------------------------------------------------------------------
extern "C" void kernel_launch(void* const* d_in, const int* in_sizes, int n_in,
                              void* d_out, int out_size) {
    const float* x  = (const float*)d_in[0];
    const void*  ei = d_in[1];
    const float* W1 = (const float*)d_in[2];
    const float* b1 = (const float*)d_in[3];
    const float* W2 = (const float*)d_in[4];
    const float* b2 = (const float*)d_in[5];
    float* out = (float*)d_out;

    int n = in_sizes[0] / 128;
    int e = in_sizes[1] / 2;

    // Graph prep
    k_detect<<<1, 32>>>((const unsigned int*)ei);
    k_deg_init<<<(n + 255) / 256, 256>>>(n);
    k_count<<<(e + 255) / 256, 256>>>(ei, e, n);
    k_scan<<<1, 1024>>>(n);
    k_fill<<<(e + 255) / 256, 256>>>(ei, e, n);

    // Layer 1
    k_gemm1<<<(n + 31) / 32, 256>>>(x, W1, n);
    k_agg<false><<<(n + 3) / 4, 256>>>(n, nullptr, nullptr);

    // Layer 2 (relu + b1 fused into GEMM2 smem load)
    k_gemm2<<<(n + 31) / 32, 256>>>(W2, b1, n);
    k_agg<true><<<(n + 3) / 4, 256>>>(n, b2, out);
}

// round 5
// speedup vs baseline: 1.8713x; 1.8713x over previous
#include <cuda_runtime.h>

#define NMAX 100000
#define EMAX 1600000
#define SCAN_BLK 256
#define MAX_BLOCKS 512   // ceil(NMAX/SCAN_BLK) = 391 <= 512

// Scratch (allocation-free rule: __device__ globals)
__device__ int   g_is64;           // 1 if edge_index buffer is int64, else int32
__device__ int   g_deg[NMAX];      // in-degree incl self-loop
__device__ float g_dinv[NMAX];
__device__ int   g_off[NMAX];      // CSR row start (real edges only)
__device__ int   g_cur[NMAX];      // fill cursors
__device__ int   g_bsum[MAX_BLOCKS];
__device__ int   g_csr[EMAX];      // src node per CSR slot
__device__ float g_t[NMAX * 64];   // t1 = x@W1, later t2 = relu(h)@W2
__device__ float g_h[NMAX * 64];   // layer-1 aggregated output

// ---------------------------------------------------------------------------
// Detect int32 vs int64 edge_index (parallel). Node ids < 100000 fit in 32
// bits, so a genuine int64 buffer has every odd 32-bit word == 0.
__global__ void k_detect(const unsigned int* __restrict__ w) {
    int t = threadIdx.x;
    int nz = (w[2 * t + 1] != 0u) ? 1 : 0;
    int tot = __syncthreads_count(nz);
    if (t == 0) g_is64 = (tot == 0) ? 1 : 0;
}

__device__ __forceinline__ int load_idx(const void* ei, long long i) {
    if (g_is64) return (int)((const long long*)ei)[i];
    return ((const int*)ei)[i];
}

__global__ void k_deg_init(int n) {
    int i = blockIdx.x * blockDim.x + threadIdx.x;
    if (i < n) g_deg[i] = 1;  // self-loop
}

__global__ void k_count(const void* __restrict__ ei, int e, int n) {
    int i = blockIdx.x * blockDim.x + threadIdx.x;
    if (i >= e) return;
    int d = load_idx(ei, (long long)e + i);
    if ((unsigned)d < (unsigned)n) atomicAdd(&g_deg[d], 1);
}

// --- 3-phase grid-wide exclusive scan of (deg-1) ---------------------------
// Phase 1: per-block sums.
__global__ void k_scan1(int n) {
    __shared__ int sh[SCAN_BLK];
    int t = threadIdx.x;
    int i = blockIdx.x * SCAN_BLK + t;
    sh[t] = (i < n) ? (g_deg[i] - 1) : 0;
    __syncthreads();
    for (int s = SCAN_BLK / 2; s > 0; s >>= 1) {
        if (t < s) sh[t] += sh[t + s];
        __syncthreads();
    }
    if (t == 0) g_bsum[blockIdx.x] = sh[0];
}

// Phase 2: single block scans the <=512 block sums (inclusive -> exclusive).
__global__ void k_scan2(int nb) {
    __shared__ int sh[MAX_BLOCKS];
    int t = threadIdx.x;
    int v = (t < nb) ? g_bsum[t] : 0;
    sh[t] = v;
    __syncthreads();
    for (int ofs = 1; ofs < MAX_BLOCKS; ofs <<= 1) {
        int add = (t >= ofs) ? sh[t - ofs] : 0;
        __syncthreads();
        sh[t] += add;
        __syncthreads();
    }
    if (t < nb) g_bsum[t] = sh[t] - v;   // exclusive
}

// Phase 3: per-block local exclusive scan + block offset; also dinv.
__global__ void k_scan3(int n) {
    __shared__ int sh[SCAN_BLK];
    int t = threadIdx.x;
    int i = blockIdx.x * SCAN_BLK + t;
    int d = (i < n) ? g_deg[i] : 1;
    int v = d - 1;
    sh[t] = v;
    __syncthreads();
    for (int ofs = 1; ofs < SCAN_BLK; ofs <<= 1) {
        int add = (t >= ofs) ? sh[t - ofs] : 0;
        __syncthreads();
        sh[t] += add;
        __syncthreads();
    }
    if (i < n) {
        int off = g_bsum[blockIdx.x] + sh[t] - v;  // exclusive
        g_off[i] = off;
        g_cur[i] = off;
        g_dinv[i] = rsqrtf((float)d);
    }
}

__global__ void k_fill(const void* __restrict__ ei, int e, int n) {
    int i = blockIdx.x * blockDim.x + threadIdx.x;
    if (i >= e) return;
    int s = load_idx(ei, i);
    int d = load_idx(ei, (long long)e + i);
    if ((unsigned)s >= (unsigned)n || (unsigned)d >= (unsigned)n) return;
    int pos = atomicAdd(&g_cur[d], 1);
    if ((unsigned)pos < (unsigned)EMAX) g_csr[pos] = s;
}

// ---------------------------------------------------------------------------
// GEMM1: g_t = x @ W1   (x: [n,128], W1: [128,64])
__global__ void k_gemm1(const float* __restrict__ x, const float* __restrict__ W,
                        int n) {
    __shared__ float xs[32 * 129];
    __shared__ float ws[64 * 64];
    int tx = threadIdx.x;
    int row0 = blockIdx.x * 32;

    for (int i = tx; i < 32 * 128; i += 256) {
        int r = i >> 7, k = i & 127;
        int gr = row0 + r;
        xs[r * 129 + k] = (gr < n) ? x[gr * 128 + k] : 0.f;
    }

    int c = tx & 63, y = tx >> 6;
    float acc[8];
#pragma unroll
    for (int i = 0; i < 8; i++) acc[i] = 0.f;

    for (int kb = 0; kb < 128; kb += 64) {
        __syncthreads();
        for (int i = tx; i < 64 * 64; i += 256) ws[i] = W[kb * 64 + i];
        __syncthreads();
        for (int k = 0; k < 64; ++k) {
            float w = ws[k * 64 + c];
#pragma unroll
            for (int i = 0; i < 8; i++)
                acc[i] += xs[(y * 8 + i) * 129 + kb + k] * w;
        }
    }
#pragma unroll
    for (int i = 0; i < 8; i++) {
        int gr = row0 + y * 8 + i;
        if (gr < n) g_t[gr * 64 + c] = acc[i];
    }
}

// GEMM2: g_t = relu(g_h + b1) @ W2   (fused relu+bias on load)
__global__ void k_gemm2(const float* __restrict__ W2, const float* __restrict__ b1,
                        int n) {
    __shared__ float hs[32 * 65];
    __shared__ float ws[64 * 64];
    int tx = threadIdx.x;
    int row0 = blockIdx.x * 32;

    for (int i = tx; i < 64 * 64; i += 256) ws[i] = W2[i];
    for (int i = tx; i < 32 * 64; i += 256) {
        int r = i >> 6, k = i & 63;
        int gr = row0 + r;
        float v = (gr < n) ? (g_h[gr * 64 + k] + b1[k]) : 0.f;
        hs[r * 65 + k] = fmaxf(v, 0.f);
    }
    __syncthreads();

    int c = tx & 63, y = tx >> 6;
    float acc[8];
#pragma unroll
    for (int i = 0; i < 8; i++) acc[i] = 0.f;

    for (int k = 0; k < 64; ++k) {
        float w = ws[k * 64 + c];
#pragma unroll
        for (int i = 0; i < 8; i++)
            acc[i] += hs[(y * 8 + i) * 65 + k] * w;
    }
#pragma unroll
    for (int i = 0; i < 8; i++) {
        int gr = row0 + y * 8 + i;
        if (gr < n) g_t[gr * 64 + c] = acc[i];
    }
}

// ---------------------------------------------------------------------------
// Pull-mode aggregation: 64 threads per dst node, thread c owns feature c.
template <bool FINAL>
__global__ void k_agg(int n, const float* __restrict__ bias,
                      float* __restrict__ out) {
    int gid = blockIdx.x * 4 + (threadIdx.x >> 6);
    int c = threadIdx.x & 63;
    if (gid >= n) return;

    float dd  = g_dinv[gid];
    float acc = g_t[gid * 64 + c] * dd;   // self-loop term (one dinv factor)
    int beg = g_off[gid];
    int end = beg + g_deg[gid] - 1;
#pragma unroll 4
    for (int k = beg; k < end; k++) {
        int s = g_csr[k];
        acc += g_t[s * 64 + c] * g_dinv[s];
    }
    acc *= dd;
    if (FINAL) out[gid * 64 + c] = acc + bias[c];
    else       g_h[gid * 64 + c] = acc;
}

// ---------------------------------------------------------------------------
extern "C" void kernel_launch(void* const* d_in, const int* in_sizes, int n_in,
                              void* d_out, int out_size) {
    const float* x  = (const float*)d_in[0];
    const void*  ei = d_in[1];
    const float* W1 = (const float*)d_in[2];
    const float* b1 = (const float*)d_in[3];
    const float* W2 = (const float*)d_in[4];
    const float* b2 = (const float*)d_in[5];
    float* out = (float*)d_out;

    int n = in_sizes[0] / 128;
    int e = in_sizes[1] / 2;
    int nb = (n + SCAN_BLK - 1) / SCAN_BLK;

    // Graph prep
    k_detect<<<1, 1024>>>((const unsigned int*)ei);
    k_deg_init<<<(n + 255) / 256, 256>>>(n);
    k_count<<<(e + 255) / 256, 256>>>(ei, e, n);
    k_scan1<<<nb, SCAN_BLK>>>(n);
    k_scan2<<<1, MAX_BLOCKS>>>(nb);
    k_scan3<<<nb, SCAN_BLK>>>(n);
    k_fill<<<(e + 255) / 256, 256>>>(ei, e, n);

    // Layer 1
    k_gemm1<<<(n + 31) / 32, 256>>>(x, W1, n);
    k_agg<false><<<(n + 3) / 4, 256>>>(n, nullptr, nullptr);

    // Layer 2 (relu + b1 fused into GEMM2 smem load)
    k_gemm2<<<(n + 31) / 32, 256>>>(W2, b1, n);
    k_agg<true><<<(n + 3) / 4, 256>>>(n, b2, out);
}

// round 6
// speedup vs baseline: 2.4944x; 1.3330x over previous
#include <cuda_runtime.h>

#define NMAX 100000
#define EMAX 1600000
#define SCAN_BLK 256
#define MAX_BLOCKS 512   // ceil(NMAX/SCAN_BLK) = 391 <= 512

// Scratch (allocation-free rule: __device__ globals)
__device__ int   g_is64;
__device__ int   g_deg[NMAX];              // in-degree incl self-loop
__device__ float g_dinv[NMAX];
__device__ int   g_off[NMAX];              // CSR row start (real edges only)
__device__ int   g_cur[NMAX];              // fill cursors
__device__ int   g_bsum[MAX_BLOCKS];
__device__ unsigned long long g_csr2[EMAX]; // packed (src | dinv[src]<<32)
__device__ float g_t[NMAX * 64];           // t1 = x@W1, later t2 = relu(h)@W2
__device__ float g_h[NMAX * 64];           // layer-1 aggregated output

// --- packed f32x2 helpers (Blackwell FFMA2) --------------------------------
__device__ __forceinline__ unsigned long long pack2(float a, float b) {
    unsigned long long r;
    asm("mov.b64 %0, {%1, %2};" : "=l"(r) : "f"(a), "f"(b));
    return r;
}
__device__ __forceinline__ unsigned long long dup2(float a) { return pack2(a, a); }
__device__ __forceinline__ void fma2(unsigned long long& d, unsigned long long a,
                                     unsigned long long b) {
    asm("fma.rn.f32x2 %0, %1, %2, %0;" : "+l"(d) : "l"(a), "l"(b));
}
__device__ __forceinline__ float2 unpack2(unsigned long long v) {
    float2 f;
    asm("mov.b64 {%0, %1}, %2;" : "=f"(f.x), "=f"(f.y) : "l"(v));
    return f;
}

// ---------------------------------------------------------------------------
__global__ void k_detect(const unsigned int* __restrict__ w) {
    int t = threadIdx.x;
    int nz = (w[2 * t + 1] != 0u) ? 1 : 0;
    int tot = __syncthreads_count(nz);
    if (t == 0) g_is64 = (tot == 0) ? 1 : 0;
}

__device__ __forceinline__ int load_idx(const void* ei, long long i) {
    if (g_is64) return (int)((const long long*)ei)[i];
    return ((const int*)ei)[i];
}

__global__ void k_deg_init(int n) {
    int i = blockIdx.x * blockDim.x + threadIdx.x;
    if (i < n) g_deg[i] = 1;  // self-loop
}

__global__ void k_count(const void* __restrict__ ei, int e, int n) {
    int i = blockIdx.x * blockDim.x + threadIdx.x;
    if (i >= e) return;
    int d = load_idx(ei, (long long)e + i);
    if ((unsigned)d < (unsigned)n) atomicAdd(&g_deg[d], 1);
}

// --- 3-phase grid-wide exclusive scan of (deg-1) ---------------------------
__global__ void k_scan1(int n) {
    __shared__ int sh[SCAN_BLK];
    int t = threadIdx.x;
    int i = blockIdx.x * SCAN_BLK + t;
    sh[t] = (i < n) ? (g_deg[i] - 1) : 0;
    __syncthreads();
    for (int s = SCAN_BLK / 2; s > 0; s >>= 1) {
        if (t < s) sh[t] += sh[t + s];
        __syncthreads();
    }
    if (t == 0) g_bsum[blockIdx.x] = sh[0];
}

__global__ void k_scan2(int nb) {
    __shared__ int sh[MAX_BLOCKS];
    int t = threadIdx.x;
    int v = (t < nb) ? g_bsum[t] : 0;
    sh[t] = v;
    __syncthreads();
    for (int ofs = 1; ofs < MAX_BLOCKS; ofs <<= 1) {
        int add = (t >= ofs) ? sh[t - ofs] : 0;
        __syncthreads();
        sh[t] += add;
        __syncthreads();
    }
    if (t < nb) g_bsum[t] = sh[t] - v;   // exclusive
}

__global__ void k_scan3(int n) {
    __shared__ int sh[SCAN_BLK];
    int t = threadIdx.x;
    int i = blockIdx.x * SCAN_BLK + t;
    int d = (i < n) ? g_deg[i] : 1;
    int v = d - 1;
    sh[t] = v;
    __syncthreads();
    for (int ofs = 1; ofs < SCAN_BLK; ofs <<= 1) {
        int add = (t >= ofs) ? sh[t - ofs] : 0;
        __syncthreads();
        sh[t] += add;
        __syncthreads();
    }
    if (i < n) {
        int off = g_bsum[blockIdx.x] + sh[t] - v;  // exclusive
        g_off[i] = off;
        g_cur[i] = off;
        g_dinv[i] = rsqrtf((float)d);
    }
}

__global__ void k_fill(const void* __restrict__ ei, int e, int n) {
    int i = blockIdx.x * blockDim.x + threadIdx.x;
    if (i >= e) return;
    int s = load_idx(ei, i);
    int d = load_idx(ei, (long long)e + i);
    if ((unsigned)s >= (unsigned)n || (unsigned)d >= (unsigned)n) return;
    int pos = atomicAdd(&g_cur[d], 1);
    if ((unsigned)pos < (unsigned)EMAX)
        g_csr2[pos] = (unsigned long long)(unsigned)s |
                      ((unsigned long long)__float_as_uint(g_dinv[s]) << 32);
}

// ---------------------------------------------------------------------------
// GEMM1: g_t = x @ W1. Block tile 128 rows x 64 cols, 256 threads.
// Thread: 4 rows (ty*4..) x 8 cols (tx*8..) = 16 outputs as 16 f32x2 accs.
// K chunked by 32. FFMA2 (packed fp32) -> ~64 cyc per k-step per SM.
__global__ void k_gemm1(const float* __restrict__ x, const float* __restrict__ W,
                        int n) {
    __shared__ float xs[128 * 33];   // [row][kk], pad 33 (conflict-free)
    __shared__ float ws[32 * 64];    // [kk][col]
    int tid = threadIdx.x;
    int row0 = blockIdx.x * 128;
    int tx = tid & 7;                // col group: cols 8*tx..8*tx+7
    int ty = tid >> 3;               // row group: rows 4*ty..4*ty+3

    unsigned long long acc[4][4];
#pragma unroll
    for (int r = 0; r < 4; r++)
#pragma unroll
        for (int c = 0; c < 4; c++) acc[r][c] = 0ull;

    int lr = tid >> 1;               // load row
    int lh = tid & 1;                // which 16-k half
    for (int kb = 0; kb < 128; kb += 32) {
        // load xs chunk: 128 rows x 32 k
        {
            const float4* xrow =
                (const float4*)(x + (long long)(row0 + lr) * 128 + kb + lh * 16);
            bool ok = (row0 + lr) < n;
#pragma unroll
            for (int q = 0; q < 4; q++) {
                float4 v = ok ? xrow[q] : make_float4(0.f, 0.f, 0.f, 0.f);
                int k0 = lh * 16 + q * 4;
                float* p = xs + lr * 33 + k0;
                p[0] = v.x; p[1] = v.y; p[2] = v.z; p[3] = v.w;
            }
        }
        // load ws chunk: 32 x 64
        {
            const float4* wsrc = (const float4*)(W + kb * 64);
            float4* wdst = (float4*)ws;
            wdst[tid] = wsrc[tid];
            wdst[tid + 256] = wsrc[tid + 256];
        }
        __syncthreads();
#pragma unroll
        for (int kk = 0; kk < 32; kk++) {
            const float4* wp = (const float4*)(ws + kk * 64 + tx * 8);
            float4 w01 = wp[0];
            float4 w23 = wp[1];
            unsigned long long wq[4];
            wq[0] = pack2(w01.x, w01.y);
            wq[1] = pack2(w01.z, w01.w);
            wq[2] = pack2(w23.x, w23.y);
            wq[3] = pack2(w23.z, w23.w);
#pragma unroll
            for (int r = 0; r < 4; r++) {
                unsigned long long xd = dup2(xs[(ty * 4 + r) * 33 + kk]);
#pragma unroll
                for (int c = 0; c < 4; c++) fma2(acc[r][c], xd, wq[c]);
            }
        }
        __syncthreads();
    }
#pragma unroll
    for (int r = 0; r < 4; r++) {
        int gr = row0 + ty * 4 + r;
        if (gr >= n) break;
        float2 a0 = unpack2(acc[r][0]), a1 = unpack2(acc[r][1]);
        float2 a2 = unpack2(acc[r][2]), a3 = unpack2(acc[r][3]);
        float4* dst = (float4*)(g_t + gr * 64 + tx * 8);
        dst[0] = make_float4(a0.x, a0.y, a1.x, a1.y);
        dst[1] = make_float4(a2.x, a2.y, a3.x, a3.y);
    }
}

// GEMM2: g_t = relu(g_h + b1) @ W2. Same structure, K=64.
__global__ void k_gemm2(const float* __restrict__ W2, const float* __restrict__ b1,
                        int n) {
    __shared__ float xs[128 * 33];
    __shared__ float ws[32 * 64];
    int tid = threadIdx.x;
    int row0 = blockIdx.x * 128;
    int tx = tid & 7;
    int ty = tid >> 3;

    unsigned long long acc[4][4];
#pragma unroll
    for (int r = 0; r < 4; r++)
#pragma unroll
        for (int c = 0; c < 4; c++) acc[r][c] = 0ull;

    int lr = tid >> 1;
    int lh = tid & 1;
    for (int kb = 0; kb < 64; kb += 32) {
        {
            const float4* hrow =
                (const float4*)(g_h + (long long)(row0 + lr) * 64 + kb + lh * 16);
            const float4* brow = (const float4*)(b1 + kb + lh * 16);
            bool ok = (row0 + lr) < n;
#pragma unroll
            for (int q = 0; q < 4; q++) {
                float4 b = brow[q];
                float4 v = ok ? hrow[q] : make_float4(0.f, 0.f, 0.f, 0.f);
                int k0 = lh * 16 + q * 4;
                float* p = xs + lr * 33 + k0;
                p[0] = fmaxf(v.x + b.x, 0.f);
                p[1] = fmaxf(v.y + b.y, 0.f);
                p[2] = fmaxf(v.z + b.z, 0.f);
                p[3] = fmaxf(v.w + b.w, 0.f);
            }
        }
        {
            const float4* wsrc = (const float4*)(W2 + kb * 64);
            float4* wdst = (float4*)ws;
            wdst[tid] = wsrc[tid];
            wdst[tid + 256] = wsrc[tid + 256];
        }
        __syncthreads();
#pragma unroll
        for (int kk = 0; kk < 32; kk++) {
            const float4* wp = (const float4*)(ws + kk * 64 + tx * 8);
            float4 w01 = wp[0];
            float4 w23 = wp[1];
            unsigned long long wq[4];
            wq[0] = pack2(w01.x, w01.y);
            wq[1] = pack2(w01.z, w01.w);
            wq[2] = pack2(w23.x, w23.y);
            wq[3] = pack2(w23.z, w23.w);
#pragma unroll
            for (int r = 0; r < 4; r++) {
                unsigned long long xd = dup2(xs[(ty * 4 + r) * 33 + kk]);
#pragma unroll
                for (int c = 0; c < 4; c++) fma2(acc[r][c], xd, wq[c]);
            }
        }
        __syncthreads();
    }
#pragma unroll
    for (int r = 0; r < 4; r++) {
        int gr = row0 + ty * 4 + r;
        if (gr >= n) break;
        float2 a0 = unpack2(acc[r][0]), a1 = unpack2(acc[r][1]);
        float2 a2 = unpack2(acc[r][2]), a3 = unpack2(acc[r][3]);
        float4* dst = (float4*)(g_t + gr * 64 + tx * 8);
        dst[0] = make_float4(a0.x, a0.y, a1.x, a1.y);
        dst[1] = make_float4(a2.x, a2.y, a3.x, a3.y);
    }
}

// ---------------------------------------------------------------------------
// Pull-mode aggregation: 16 threads per dst node, thread c owns float4 chunk c.
template <bool FINAL>
__global__ void k_agg(int n, const float* __restrict__ bias,
                      float* __restrict__ out) {
    int gid = blockIdx.x * 16 + (threadIdx.x >> 4);
    int c = threadIdx.x & 15;
    if (gid >= n) return;

    const float4* t4 = (const float4*)g_t;
    float dd = g_dinv[gid];
    float4 v = t4[gid * 16 + c];
    float4 acc = make_float4(v.x * dd, v.y * dd, v.z * dd, v.w * dd);

    int beg = g_off[gid];
    int end = beg + g_deg[gid] - 1;
#pragma unroll 4
    for (int k = beg; k < end; k++) {
        unsigned long long p = g_csr2[k];
        int s = (int)(unsigned)p;
        float w = __uint_as_float((unsigned)(p >> 32));
        float4 tv = t4[s * 16 + c];
        acc.x += tv.x * w;
        acc.y += tv.y * w;
        acc.z += tv.z * w;
        acc.w += tv.w * w;
    }
    acc.x *= dd; acc.y *= dd; acc.z *= dd; acc.w *= dd;
    if (FINAL) {
        float4 b = ((const float4*)bias)[c];
        acc.x += b.x; acc.y += b.y; acc.z += b.z; acc.w += b.w;
        ((float4*)out)[gid * 16 + c] = acc;
    } else {
        ((float4*)g_h)[gid * 16 + c] = acc;
    }
}

// ---------------------------------------------------------------------------
extern "C" void kernel_launch(void* const* d_in, const int* in_sizes, int n_in,
                              void* d_out, int out_size) {
    const float* x  = (const float*)d_in[0];
    const void*  ei = d_in[1];
    const float* W1 = (const float*)d_in[2];
    const float* b1 = (const float*)d_in[3];
    const float* W2 = (const float*)d_in[4];
    const float* b2 = (const float*)d_in[5];
    float* out = (float*)d_out;

    int n = in_sizes[0] / 128;
    int e = in_sizes[1] / 2;
    int nb = (n + SCAN_BLK - 1) / SCAN_BLK;

    // Graph prep
    k_detect<<<1, 1024>>>((const unsigned int*)ei);
    k_deg_init<<<(n + 255) / 256, 256>>>(n);
    k_count<<<(e + 255) / 256, 256>>>(ei, e, n);
    k_scan1<<<nb, SCAN_BLK>>>(n);
    k_scan2<<<1, MAX_BLOCKS>>>(nb);
    k_scan3<<<nb, SCAN_BLK>>>(n);
    k_fill<<<(e + 255) / 256, 256>>>(ei, e, n);

    // Layer 1
    k_gemm1<<<(n + 127) / 128, 256>>>(x, W1, n);
    k_agg<false><<<(n + 15) / 16, 256>>>(n, nullptr, nullptr);

    // Layer 2 (relu + b1 fused into GEMM2 smem load)
    k_gemm2<<<(n + 127) / 128, 256>>>(W2, b1, n);
    k_agg<true><<<(n + 15) / 16, 256>>>(n, b2, out);
}

// round 7
// speedup vs baseline: 2.6233x; 1.0517x over previous
#include <cuda_runtime.h>
#include <cuda_fp16.h>

#define NMAX 100000
#define EMAX 1600000
#define SCAN_BLK 256
#define MAX_BLOCKS 512   // ceil(NMAX/SCAN_BLK) = 391 <= 512

// Scratch (allocation-free rule: __device__ globals)
__device__ int   g_is64;
__device__ int   g_deg[NMAX];              // in-degree incl self-loop
__device__ float g_dinv[NMAX];
__device__ int   g_off[NMAX];              // CSR row start (real edges only)
__device__ int   g_cur[NMAX];              // fill cursors
__device__ int   g_bsum[MAX_BLOCKS];
__device__ unsigned long long g_csr2[EMAX]; // packed (src | dinv[src]<<32)
__device__ __align__(16) __half g_t16[NMAX * 64]; // t in fp16 (gather matrix)
__device__ float g_h[NMAX * 64];           // layer-1 aggregated output (fp32)

// --- packed f32x2 helpers (Blackwell FFMA2) --------------------------------
__device__ __forceinline__ unsigned long long pack2(float a, float b) {
    unsigned long long r;
    asm("mov.b64 %0, {%1, %2};" : "=l"(r) : "f"(a), "f"(b));
    return r;
}
__device__ __forceinline__ unsigned long long dup2(float a) { return pack2(a, a); }
__device__ __forceinline__ void fma2(unsigned long long& d, unsigned long long a,
                                     unsigned long long b) {
    asm("fma.rn.f32x2 %0, %1, %2, %0;" : "+l"(d) : "l"(a), "l"(b));
}
__device__ __forceinline__ float2 unpack2(unsigned long long v) {
    float2 f;
    asm("mov.b64 {%0, %1}, %2;" : "=f"(f.x), "=f"(f.y) : "l"(v));
    return f;
}

// ---------------------------------------------------------------------------
// deg init + dtype detect fused. Node ids < 100000 -> genuine int64 buffer
// has every odd 32-bit word == 0.
__global__ void k_init(const unsigned int* __restrict__ w, int n) {
    int i = blockIdx.x * 1024 + threadIdx.x;
    if (i < n) g_deg[i] = 1;  // self-loop
    if (blockIdx.x == 0) {
        int nz = (w[2 * threadIdx.x + 1] != 0u) ? 1 : 0;
        int tot = __syncthreads_count(nz);
        if (threadIdx.x == 0) g_is64 = (tot == 0) ? 1 : 0;
    }
}

__device__ __forceinline__ int load_idx(const void* ei, long long i) {
    if (g_is64) return (int)((const long long*)ei)[i];
    return ((const int*)ei)[i];
}

__global__ void k_count(const void* __restrict__ ei, int e, int n) {
    int i = blockIdx.x * blockDim.x + threadIdx.x;
    if (i >= e) return;
    int d = load_idx(ei, (long long)e + i);
    if ((unsigned)d < (unsigned)n) atomicAdd(&g_deg[d], 1);
}

// --- 3-phase grid-wide exclusive scan of (deg-1) ---------------------------
__global__ void k_scan1(int n) {
    __shared__ int sh[SCAN_BLK];
    int t = threadIdx.x;
    int i = blockIdx.x * SCAN_BLK + t;
    sh[t] = (i < n) ? (g_deg[i] - 1) : 0;
    __syncthreads();
    for (int s = SCAN_BLK / 2; s > 0; s >>= 1) {
        if (t < s) sh[t] += sh[t + s];
        __syncthreads();
    }
    if (t == 0) g_bsum[blockIdx.x] = sh[0];
}

__global__ void k_scan2(int nb) {
    __shared__ int sh[MAX_BLOCKS];
    int t = threadIdx.x;
    int v = (t < nb) ? g_bsum[t] : 0;
    sh[t] = v;
    __syncthreads();
    for (int ofs = 1; ofs < MAX_BLOCKS; ofs <<= 1) {
        int add = (t >= ofs) ? sh[t - ofs] : 0;
        __syncthreads();
        sh[t] += add;
        __syncthreads();
    }
    if (t < nb) g_bsum[t] = sh[t] - v;   // exclusive
}

__global__ void k_scan3(int n) {
    __shared__ int sh[SCAN_BLK];
    int t = threadIdx.x;
    int i = blockIdx.x * SCAN_BLK + t;
    int d = (i < n) ? g_deg[i] : 1;
    int v = d - 1;
    sh[t] = v;
    __syncthreads();
    for (int ofs = 1; ofs < SCAN_BLK; ofs <<= 1) {
        int add = (t >= ofs) ? sh[t - ofs] : 0;
        __syncthreads();
        sh[t] += add;
        __syncthreads();
    }
    if (i < n) {
        int off = g_bsum[blockIdx.x] + sh[t] - v;  // exclusive
        g_off[i] = off;
        g_cur[i] = off;
        g_dinv[i] = rsqrtf((float)d);
    }
}

__global__ void k_fill(const void* __restrict__ ei, int e, int n) {
    int i = blockIdx.x * blockDim.x + threadIdx.x;
    if (i >= e) return;
    int s = load_idx(ei, i);
    int d = load_idx(ei, (long long)e + i);
    if ((unsigned)s >= (unsigned)n || (unsigned)d >= (unsigned)n) return;
    int pos = atomicAdd(&g_cur[d], 1);
    if ((unsigned)pos < (unsigned)EMAX)
        g_csr2[pos] = (unsigned long long)(unsigned)s |
                      ((unsigned long long)__float_as_uint(g_dinv[s]) << 32);
}

// --- fp16 epilogue pack ----------------------------------------------------
__device__ __forceinline__ uint4 pack8h(float2 a0, float2 a1, float2 a2, float2 a3) {
    uint4 u;
    __half2 h0 = __float22half2_rn(a0);
    __half2 h1 = __float22half2_rn(a1);
    __half2 h2 = __float22half2_rn(a2);
    __half2 h3 = __float22half2_rn(a3);
    u.x = *(unsigned*)&h0; u.y = *(unsigned*)&h1;
    u.z = *(unsigned*)&h2; u.w = *(unsigned*)&h3;
    return u;
}

// ---------------------------------------------------------------------------
// GEMM1: g_t16 = half(x @ W1). Block tile 128x64, 256 threads, FFMA2.
__global__ void k_gemm1(const float* __restrict__ x, const float* __restrict__ W,
                        int n) {
    __shared__ float xs[128 * 33];
    __shared__ float ws[32 * 64];
    int tid = threadIdx.x;
    int row0 = blockIdx.x * 128;
    int tx = tid & 7;
    int ty = tid >> 3;

    unsigned long long acc[4][4];
#pragma unroll
    for (int r = 0; r < 4; r++)
#pragma unroll
        for (int c = 0; c < 4; c++) acc[r][c] = 0ull;

    int lr = tid >> 1;
    int lh = tid & 1;
    for (int kb = 0; kb < 128; kb += 32) {
        {
            const float4* xrow =
                (const float4*)(x + (long long)(row0 + lr) * 128 + kb + lh * 16);
            bool ok = (row0 + lr) < n;
#pragma unroll
            for (int q = 0; q < 4; q++) {
                float4 v = ok ? xrow[q] : make_float4(0.f, 0.f, 0.f, 0.f);
                int k0 = lh * 16 + q * 4;
                float* p = xs + lr * 33 + k0;
                p[0] = v.x; p[1] = v.y; p[2] = v.z; p[3] = v.w;
            }
        }
        {
            const float4* wsrc = (const float4*)(W + kb * 64);
            float4* wdst = (float4*)ws;
            wdst[tid] = wsrc[tid];
            wdst[tid + 256] = wsrc[tid + 256];
        }
        __syncthreads();
#pragma unroll
        for (int kk = 0; kk < 32; kk++) {
            const float4* wp = (const float4*)(ws + kk * 64 + tx * 8);
            float4 w01 = wp[0];
            float4 w23 = wp[1];
            unsigned long long wq[4];
            wq[0] = pack2(w01.x, w01.y);
            wq[1] = pack2(w01.z, w01.w);
            wq[2] = pack2(w23.x, w23.y);
            wq[3] = pack2(w23.z, w23.w);
#pragma unroll
            for (int r = 0; r < 4; r++) {
                unsigned long long xd = dup2(xs[(ty * 4 + r) * 33 + kk]);
#pragma unroll
                for (int c = 0; c < 4; c++) fma2(acc[r][c], xd, wq[c]);
            }
        }
        __syncthreads();
    }
#pragma unroll
    for (int r = 0; r < 4; r++) {
        int gr = row0 + ty * 4 + r;
        if (gr >= n) break;
        uint4 u = pack8h(unpack2(acc[r][0]), unpack2(acc[r][1]),
                         unpack2(acc[r][2]), unpack2(acc[r][3]));
        *(uint4*)(g_t16 + gr * 64 + tx * 8) = u;
    }
}

// GEMM2: g_t16 = half(relu(g_h + b1) @ W2). K=64.
__global__ void k_gemm2(const float* __restrict__ W2, const float* __restrict__ b1,
                        int n) {
    __shared__ float xs[128 * 33];
    __shared__ float ws[32 * 64];
    int tid = threadIdx.x;
    int row0 = blockIdx.x * 128;
    int tx = tid & 7;
    int ty = tid >> 3;

    unsigned long long acc[4][4];
#pragma unroll
    for (int r = 0; r < 4; r++)
#pragma unroll
        for (int c = 0; c < 4; c++) acc[r][c] = 0ull;

    int lr = tid >> 1;
    int lh = tid & 1;
    for (int kb = 0; kb < 64; kb += 32) {
        {
            const float4* hrow =
                (const float4*)(g_h + (long long)(row0 + lr) * 64 + kb + lh * 16);
            const float4* brow = (const float4*)(b1 + kb + lh * 16);
            bool ok = (row0 + lr) < n;
#pragma unroll
            for (int q = 0; q < 4; q++) {
                float4 b = brow[q];
                float4 v = ok ? hrow[q] : make_float4(0.f, 0.f, 0.f, 0.f);
                int k0 = lh * 16 + q * 4;
                float* p = xs + lr * 33 + k0;
                p[0] = fmaxf(v.x + b.x, 0.f);
                p[1] = fmaxf(v.y + b.y, 0.f);
                p[2] = fmaxf(v.z + b.z, 0.f);
                p[3] = fmaxf(v.w + b.w, 0.f);
            }
        }
        {
            const float4* wsrc = (const float4*)(W2 + kb * 64);
            float4* wdst = (float4*)ws;
            wdst[tid] = wsrc[tid];
            wdst[tid + 256] = wsrc[tid + 256];
        }
        __syncthreads();
#pragma unroll
        for (int kk = 0; kk < 32; kk++) {
            const float4* wp = (const float4*)(ws + kk * 64 + tx * 8);
            float4 w01 = wp[0];
            float4 w23 = wp[1];
            unsigned long long wq[4];
            wq[0] = pack2(w01.x, w01.y);
            wq[1] = pack2(w01.z, w01.w);
            wq[2] = pack2(w23.x, w23.y);
            wq[3] = pack2(w23.z, w23.w);
#pragma unroll
            for (int r = 0; r < 4; r++) {
                unsigned long long xd = dup2(xs[(ty * 4 + r) * 33 + kk]);
#pragma unroll
                for (int c = 0; c < 4; c++) fma2(acc[r][c], xd, wq[c]);
            }
        }
        __syncthreads();
    }
#pragma unroll
    for (int r = 0; r < 4; r++) {
        int gr = row0 + ty * 4 + r;
        if (gr >= n) break;
        uint4 u = pack8h(unpack2(acc[r][0]), unpack2(acc[r][1]),
                         unpack2(acc[r][2]), unpack2(acc[r][3]));
        *(uint4*)(g_t16 + gr * 64 + tx * 8) = u;
    }
}

// ---------------------------------------------------------------------------
// Pull aggregation: 8 threads per dst node, lane c owns 8 features (one 16B
// fp16 load per gathered row). fp32 accumulate.
__device__ __forceinline__ void acc8(float acc[8], uint4 v, float w) {
    const __half2* h = (const __half2*)&v;
#pragma unroll
    for (int q = 0; q < 4; q++) {
        float2 f = __half22float2(h[q]);
        acc[2 * q]     += f.x * w;
        acc[2 * q + 1] += f.y * w;
    }
}

template <bool FINAL>
__global__ void k_agg(int n, const float* __restrict__ bias,
                      float* __restrict__ out) {
    int gid = blockIdx.x * 32 + (threadIdx.x >> 3);
    int c = threadIdx.x & 7;
    if (gid >= n) return;

    const uint4* t4 = (const uint4*)g_t16;   // 8 halves per uint4, 8 per row
    float dd = g_dinv[gid];
    float acc[8];
#pragma unroll
    for (int q = 0; q < 8; q++) acc[q] = 0.f;
    acc8(acc, t4[gid * 8 + c], dd);          // self-loop (one dinv factor)

    int beg = g_off[gid];
    int end = beg + g_deg[gid] - 1;
#pragma unroll 4
    for (int k = beg; k < end; k++) {
        unsigned long long p = g_csr2[k];
        int s = (int)(unsigned)p;
        float w = __uint_as_float((unsigned)(p >> 32));
        acc8(acc, t4[s * 8 + c], w);
    }

    float4 o0 = make_float4(acc[0] * dd, acc[1] * dd, acc[2] * dd, acc[3] * dd);
    float4 o1 = make_float4(acc[4] * dd, acc[5] * dd, acc[6] * dd, acc[7] * dd);
    if (FINAL) {
        float4 b0 = ((const float4*)bias)[c * 2];
        float4 b1v = ((const float4*)bias)[c * 2 + 1];
        o0.x += b0.x; o0.y += b0.y; o0.z += b0.z; o0.w += b0.w;
        o1.x += b1v.x; o1.y += b1v.y; o1.z += b1v.z; o1.w += b1v.w;
        float4* dst = (float4*)(out + gid * 64 + c * 8);
        dst[0] = o0; dst[1] = o1;
    } else {
        float4* dst = (float4*)(g_h + gid * 64 + c * 8);
        dst[0] = o0; dst[1] = o1;
    }
}

// ---------------------------------------------------------------------------
extern "C" void kernel_launch(void* const* d_in, const int* in_sizes, int n_in,
                              void* d_out, int out_size) {
    const float* x  = (const float*)d_in[0];
    const void*  ei = d_in[1];
    const float* W1 = (const float*)d_in[2];
    const float* b1 = (const float*)d_in[3];
    const float* W2 = (const float*)d_in[4];
    const float* b2 = (const float*)d_in[5];
    float* out = (float*)d_out;

    int n = in_sizes[0] / 128;
    int e = in_sizes[1] / 2;
    int nb = (n + SCAN_BLK - 1) / SCAN_BLK;

    // Graph prep
    k_init<<<(n + 1023) / 1024, 1024>>>((const unsigned int*)ei, n);
    k_count<<<(e + 255) / 256, 256>>>(ei, e, n);
    k_scan1<<<nb, SCAN_BLK>>>(n);
    k_scan2<<<1, MAX_BLOCKS>>>(nb);
    k_scan3<<<nb, SCAN_BLK>>>(n);
    k_fill<<<(e + 255) / 256, 256>>>(ei, e, n);

    // Layer 1
    k_gemm1<<<(n + 127) / 128, 256>>>(x, W1, n);
    k_agg<false><<<(n + 31) / 32, 256>>>(n, nullptr, nullptr);

    // Layer 2 (relu + b1 fused into GEMM2 smem load)
    k_gemm2<<<(n + 127) / 128, 256>>>(W2, b1, n);
    k_agg<true><<<(n + 31) / 32, 256>>>(n, b2, out);
}